// round 3
// baseline (speedup 1.0000x reference)
#include <cuda_runtime.h>

// Fused depthwise: y = gauss_valid( fd_valid(x) )  ==  13-tap valid FIR with
// composed weights w[k] = sum_{i+j=k} fd[i]*g[j]  (XLA conv = cross-correlation,
// both kernels applied in the same direction, so composition is plain
// polynomial-coefficient convolution).
//
// x: [8,4,T] f32 contiguous -> 32 rows of length T.  out rows: T-12.

#define BLOCK 256
#define VPT   4                    // outputs per thread
#define TILE  (BLOCK * VPT)        // 1024 outputs per block
#define HALO  12
#define SMEM_N (TILE + HALO + 4)   // 1040 floats, float4-multiple

__global__ __launch_bounds__(BLOCK)
void fused_fir13_kernel(const float* __restrict__ x,
                        const float* __restrict__ fd,   // 5 taps
                        const float* __restrict__ g,    // 9 taps
                        float* __restrict__ out,
                        int T, int Tout, int tilesPerRow)
{
    __shared__ float w[16];
    __shared__ float s[SMEM_N];

    const int tid  = threadIdx.x;
    const int bid  = blockIdx.x;
    const int row  = bid / tilesPerRow;
    const int tile = bid - row * tilesPerRow;

    // Compose the 13-tap kernel (cheap: 13 threads, <=5 FMA each; fd/g hit L2).
    if (tid < 13) {
        float acc = 0.f;
        const int lo = tid > 8 ? tid - 8 : 0;
        const int hi = tid < 4 ? tid : 4;
        for (int i = lo; i <= hi; ++i) acc += fd[i] * g[tid - i];
        w[tid] = acc;
    }

    const long long rowBase = (long long)row * T;
    const int start = tile * TILE;

    // Stage input tile [start, start + SMEM_N) into shared memory via float4.
    const int nvec = SMEM_N / 4;  // 260
    for (int i = tid; i < nvec; i += BLOCK) {
        const int gidx = start + i * 4;
        if (gidx + 3 < T) {
            ((float4*)s)[i] = *(const float4*)(x + rowBase + gidx);
        } else {
            #pragma unroll
            for (int j = 0; j < 4; ++j) {
                const int gi = gidx + j;
                s[i * 4 + j] = (gi < T) ? x[rowBase + gi] : 0.f;
            }
        }
    }
    __syncthreads();

    const int o    = tid * VPT;      // local output offset (multiple of 4)
    const int gout = start + o;
    if (gout >= Tout) return;

    // Pull 16 floats (4 float4, 16B lane stride -> conflict-free LDS.128).
    float r[VPT + HALO];
    #pragma unroll
    for (int q = 0; q < 4; ++q) {
        float4 v = ((const float4*)(s + o))[q];
        r[q * 4 + 0] = v.x; r[q * 4 + 1] = v.y;
        r[q * 4 + 2] = v.z; r[q * 4 + 3] = v.w;
    }

    float acc0 = 0.f, acc1 = 0.f, acc2 = 0.f, acc3 = 0.f;
    #pragma unroll
    for (int k = 0; k < 13; ++k) {
        const float wk = w[k];
        acc0 = fmaf(r[k + 0], wk, acc0);
        acc1 = fmaf(r[k + 1], wk, acc1);
        acc2 = fmaf(r[k + 2], wk, acc2);
        acc3 = fmaf(r[k + 3], wk, acc3);
    }

    const long long outBase = (long long)row * Tout;
    if (gout + VPT <= Tout) {
        *(float4*)(out + outBase + gout) = make_float4(acc0, acc1, acc2, acc3);
    } else {
        float a[VPT] = {acc0, acc1, acc2, acc3};
        for (int v = 0; v < VPT && gout + v < Tout; ++v)
            out[outBase + gout + v] = a[v];
    }
}

extern "C" void kernel_launch(void* const* d_in, const int* in_sizes, int n_in,
                              void* d_out, int out_size)
{
    const float* x  = (const float*)d_in[0];
    const float* fd = (const float*)d_in[1];   // 5 elements
    const float* g  = (const float*)d_in[2];   // 9 elements
    float* out = (float*)d_out;

    const int ROWS = 32;                       // 8 * 4
    const int T    = in_sizes[0] / ROWS;       // 1048576
    const int Tout = T - 12;                   // 1048564

    const int tilesPerRow = (Tout + TILE - 1) / TILE;
    const int blocks = ROWS * tilesPerRow;

    fused_fir13_kernel<<<blocks, BLOCK>>>(x, fd, g, out, T, Tout, tilesPerRow);
}

// round 4
// speedup vs baseline: 1.2673x; 1.2673x over previous
#include <cuda_runtime.h>

// Fused depthwise conv: y = gauss_valid(fd_valid(x)) == one 13-tap valid FIR
// with composed weights w[k] = sum_{i+j=k} fd[i]*g[j].
//
// x: [8,4,T] f32 contiguous -> 32 rows of length T = 1048576. out rows: T-12.
//
// R3: direct-LDG streaming (no data smem, no staging barrier). Each thread
// computes 2 groups of 4 contiguous outputs; loads are warp-contiguous
// float4 (full-line L1 wavefronts), halo overlap between threads is an L1
// hit. 8 independent LDG.128 in flight per thread before first use.

#define BLOCK  256
#define GROUPS 2
#define GTILE  (BLOCK * 4)        // 1024 outputs per group
#define TILE   (GTILE * GROUPS)   // 2048 outputs per block

__global__ __launch_bounds__(BLOCK)
void fused_fir13_direct(const float* __restrict__ x,
                        const float* __restrict__ fd,   // 5 taps
                        const float* __restrict__ gk,   // 9 taps
                        float* __restrict__ out,
                        int T, int Tout, int tilesPerRow)
{
    __shared__ float w[13];

    const int tid  = threadIdx.x;
    const int bid  = blockIdx.x;
    const int row  = bid / tilesPerRow;
    const int tile = bid - row * tilesPerRow;

    const long long xb = (long long)row * T;
    const long long ob = (long long)row * Tout;
    const int start = tile * TILE;

    // ---- Issue all data loads first (8 LDG.128 in flight per thread) ----
    float r[GROUPS][16];
    #pragma unroll
    for (int q = 0; q < GROUPS; ++q) {
        const int gb = start + q * GTILE + tid * 4;
        if (gb + 16 <= T) {
            #pragma unroll
            for (int v = 0; v < 4; ++v) {
                float4 f = *(const float4*)(x + xb + gb + 4 * v);
                r[q][4*v+0] = f.x; r[q][4*v+1] = f.y;
                r[q][4*v+2] = f.z; r[q][4*v+3] = f.w;
            }
        } else {
            #pragma unroll
            for (int i = 0; i < 16; ++i) {
                const int gi = gb + i;
                r[q][i] = (gi < T) ? x[xb + gi] : 0.f;
            }
        }
    }

    // ---- Compose 13-tap weights (overlaps with the in-flight data LDGs) ----
    if (tid < 13) {
        float acc = 0.f;
        const int lo = tid > 8 ? tid - 8 : 0;
        const int hi = tid < 4 ? tid : 4;
        for (int i = lo; i <= hi; ++i) acc += fd[i] * gk[tid - i];
        w[tid] = acc;
    }
    __syncthreads();

    float wr[13];
    #pragma unroll
    for (int k = 0; k < 13; ++k) wr[k] = w[k];

    // ---- Compute + store ----
    #pragma unroll
    for (int q = 0; q < GROUPS; ++q) {
        const int gb = start + q * GTILE + tid * 4;
        float a0 = 0.f, a1 = 0.f, a2 = 0.f, a3 = 0.f;
        #pragma unroll
        for (int k = 0; k < 13; ++k) {
            const float wk = wr[k];
            a0 = fmaf(r[q][k + 0], wk, a0);
            a1 = fmaf(r[q][k + 1], wk, a1);
            a2 = fmaf(r[q][k + 2], wk, a2);
            a3 = fmaf(r[q][k + 3], wk, a3);
        }
        if (gb + 4 <= Tout) {
            *(float4*)(out + ob + gb) = make_float4(a0, a1, a2, a3);
        } else {
            float a[4] = {a0, a1, a2, a3};
            #pragma unroll
            for (int v = 0; v < 4; ++v)
                if (gb + v < Tout) out[ob + gb + v] = a[v];
        }
    }
}

extern "C" void kernel_launch(void* const* d_in, const int* in_sizes, int n_in,
                              void* d_out, int out_size)
{
    const float* x  = (const float*)d_in[0];
    const float* fd = (const float*)d_in[1];   // 5 elements
    const float* gk = (const float*)d_in[2];   // 9 elements
    float* out = (float*)d_out;

    const int ROWS = 32;                       // 8 * 4
    const int T    = in_sizes[0] / ROWS;       // 1048576
    const int Tout = T - 12;                   // 1048564

    const int tilesPerRow = (Tout + TILE - 1) / TILE;   // 512
    const int blocks = ROWS * tilesPerRow;              // 16384

    fused_fir13_direct<<<blocks, BLOCK>>>(x, fd, gk, out, T, Tout, tilesPerRow);
}